// round 15
// baseline (speedup 1.0000x reference)
#include <cuda_runtime.h>
#include <cuda_bf16.h>
#include <cstdint>

// ---------------------------------------------------------------------------
// RPN: fused GEMM+decode -> top-12000 radix select -> cluster-parallel bitonic
// sort (8 CTAs/batch) -> cluster-parallel chunked NMS (8 CTAs/batch,
// CHUNK=1024, warp-specialized overlap: phase-3 sweep on warp 0 runs
// concurrently with next-chunk load + prevet on warps 1-31).
// Outputs: rpn_locs[8,36864,4] | rpn_scores[8,36864,2] | rois[8,600,4] | anchor[1,36864,4]
// Score GEMM accumulation = splitK2 (bit-matches reference); loc GEMM = plain chain.
// ---------------------------------------------------------------------------

#define NB        8
#define NA        36864
#define HW        4096
#define K_DIM     512
#define N_PRE     12000
#define N_POST    600
#define SORT_N    16384

#define OFF_SCORES 1179648
#define OFF_ROIS   1769472
#define OFF_ANCH   1788672

__device__ float4             g_boxes[NB][NA];
__device__ unsigned           g_su[NB][NA];
__device__ unsigned long long g_cand[NB][SORT_N];
__device__ int                g_C[NB];
__device__ int                g_vcnt[NB];
__device__ float4             g_sboxes[NB][N_PRE];
__device__ unsigned           g_deadw[NB][2][8][4];      // 128 dead bits per rank
__device__ unsigned           g_supg[2][NB][1024 * 32];  // phase-2 sup exchange (split path)
__device__ unsigned long long g_sbuf[2][NB][SORT_N];     // sort cross-CTA ping-pong

__constant__ float c_aw[9] = {181.01933598375618f, 362.03867196751236f, 724.0773439350247f,
                              128.0f, 256.0f, 512.0f,
                              90.50966799187809f, 181.01933598375618f, 362.03867196751236f};
__constant__ float c_ah[9] = {90.50966799187809f, 181.01933598375618f, 362.03867196751236f,
                              128.0f, 256.0f, 512.0f,
                              181.01933598375618f, 362.03867196751236f, 724.0773439350247f};

// ---------------------------------------------------------------------------
// packed f32x2 helpers
// ---------------------------------------------------------------------------
__device__ __forceinline__ unsigned long long fma2(unsigned long long a,
                                                   unsigned long long b,
                                                   unsigned long long c)
{
    unsigned long long d;
    asm("fma.rn.f32x2 %0, %1, %2, %3;" : "=l"(d) : "l"(a), "l"(b), "l"(c));
    return d;
}
__device__ __forceinline__ unsigned long long packxx(float x)
{
    unsigned long long r;
    unsigned xi = __float_as_uint(x);
    asm("mov.b64 %0, {%1, %2};" : "=l"(r) : "r"(xi), "r"(xi));
    return r;
}
__device__ __forceinline__ float f2lo(unsigned long long u) { return __uint_as_float((unsigned)u); }
__device__ __forceinline__ float f2hi(unsigned long long u) { return __uint_as_float((unsigned)(u >> 32)); }

__device__ __forceinline__ void gemm_inner(const float* xs,
                                           const unsigned long long* ws2, int t,
                                           unsigned long long (&accp)[18],
                                           unsigned long long (&scp)[9])
{
#pragma unroll 4
    for (int kk = 0; kk < 64; kk++) {
        unsigned long long xp = packxx(xs[kk * 128 + t]);
#pragma unroll
        for (int o2 = 0; o2 < 18; o2++)
            accp[o2] = fma2(ws2[o2 * 64 + kk], xp, accp[o2]);
#pragma unroll
        for (int o2 = 0; o2 < 9; o2++)
            scp[o2] = fma2(ws2[(18 + o2) * 64 + kk], xp, scp[o2]);
    }
}

// ---------------------------------------------------------------------------
// K1: fused GEMM + decode epilogue (unchanged)
// ---------------------------------------------------------------------------
__global__ __launch_bounds__(128) void gemm_kernel(
    const float* __restrict__ x,
    const float* __restrict__ wsc, const float* __restrict__ bsc,
    const float* __restrict__ wlc, const float* __restrict__ blc,
    float* __restrict__ out)
{
    __shared__ float xs[64 * 128];
    __shared__ unsigned long long ws2[27 * 64];
    const int t   = threadIdx.x;
    const int b   = blockIdx.x;
    const int n   = b >> 5;
    const int hw0 = (b & 31) * 128;
    const float* xb = x + n * (K_DIM * HW) + hw0;

    unsigned long long accp[18], sp0[9], sp1[9];
#pragma unroll
    for (int o = 0; o < 18; o++) accp[o] = 0ull;
#pragma unroll
    for (int o = 0; o < 9; o++) { sp0[o] = 0ull; sp1[o] = 0ull; }

    for (int k0 = 0; k0 < K_DIM; k0 += 64) {
#pragma unroll
        for (int it = 0; it < 16; it++) {
            int v = t + it * 128;
            int r = v >> 5;
            int c = v & 31;
            float4 val = *(const float4*)(xb + (k0 + r) * HW + c * 4);
            *(float4*)&xs[r * 128 + c * 4] = val;
        }
        for (int v = t; v < 864; v += 128) {
            int o = v >> 4;
            int c = v & 15;
            const float* row = (o < 36) ? (wlc + o * K_DIM) : (wsc + (o - 36) * K_DIM);
            float4 w = *(const float4*)(row + k0 + c * 4);
            float* dst = (float*)&ws2[(o >> 1) * 64 + c * 4];
            int half = o & 1;
            dst[0 + half] = w.x;
            dst[2 + half] = w.y;
            dst[4 + half] = w.z;
            dst[6 + half] = w.w;
        }
        __syncthreads();

        if (k0 < 256) gemm_inner(xs, ws2, t, accp, sp0);
        else          gemm_inner(xs, ws2, t, accp, sp1);
        __syncthreads();
    }

    const int hw = hw0 + t;
    float lv[36], sv[18];
#pragma unroll
    for (int o2 = 0; o2 < 18; o2++) {
        lv[2 * o2]     = f2lo(accp[o2]) + blc[2 * o2];
        lv[2 * o2 + 1] = f2hi(accp[o2]) + blc[2 * o2 + 1];
    }
#pragma unroll
    for (int o2 = 0; o2 < 9; o2++) {
        sv[2 * o2]     = (f2lo(sp0[o2]) + f2lo(sp1[o2])) + bsc[2 * o2];
        sv[2 * o2 + 1] = (f2hi(sp0[o2]) + f2hi(sp1[o2])) + bsc[2 * o2 + 1];
    }

    float* lout = out + n * (NA * 4) + hw * 36;
#pragma unroll
    for (int o = 0; o < 36; o++) lout[o] = lv[o];
    float* sout = out + OFF_SCORES + n * (NA * 2) + hw * 18;
#pragma unroll
    for (int o = 0; o < 18; o++) sout[o] = sv[o];

    float sx = (float)((hw & 63) * 16);
    float sy = (float)((hw >> 6) * 16);
#pragma unroll
    for (int a = 0; a < 9; a++) {
        int i = hw * 9 + a;
        float aw = c_aw[a], ah = c_ah[a];
        float ax1 = sx - 0.5f * aw, ay1 = sy - 0.5f * ah;
        float ax2 = sx + 0.5f * aw, ay2 = sy + 0.5f * ah;
        if (n == 0)
            *(float4*)(out + OFF_ANCH + i * 4) = make_float4(ax1, ay1, ax2, ay2);

        float aww = ax2 - ax1, ahh = ay2 - ay1;
        float acx = ax1 + 0.5f * aww, acy = ay1 + 0.5f * ahh;

        float cx = lv[a * 4 + 0] * aww + acx;
        float cy = lv[a * 4 + 1] * ahh + acy;
        float w  = expf(lv[a * 4 + 2]) * aww;
        float h  = expf(lv[a * 4 + 3]) * ahh;

        float x1 = fminf(fmaxf(cx - 0.5f * w, 0.0f), 1024.0f);
        float y1 = fminf(fmaxf(cy - 0.5f * h, 0.0f), 1024.0f);
        float x2 = fminf(fmaxf(cx + 0.5f * w, 0.0f), 1024.0f);
        float y2 = fminf(fmaxf(cy + 0.5f * h, 0.0f), 1024.0f);

        bool valid = ((x2 - x1) >= 16.0f) && ((y2 - y1) >= 16.0f);

        float s0 = sv[a * 2], s1 = sv[a * 2 + 1];
        float m  = fmaxf(s0, s1);
        float e0 = expf(s0 - m), e1 = expf(s1 - m);
        float fg = e1 / (e0 + e1);

        g_su[n][i]    = valid ? (__float_as_uint(fg) | 0x80000000u) : 0u;
        g_boxes[n][i] = make_float4(x1, y1, x2, y2);
    }
}

// ---------------------------------------------------------------------------
// K3: radix select (unchanged)
// ---------------------------------------------------------------------------
__global__ __launch_bounds__(1024) void select_kernel()
{
    __shared__ unsigned hist[4096];
    __shared__ unsigned psum[256];
    __shared__ int sB1, sAbove, sThr, sCnt;

    const int n = blockIdx.x;
    const int t = threadIdx.x;

    for (int v = t; v < 4096; v += 1024) hist[v] = 0;
    __syncthreads();
    for (int i = t; i < NA; i += 1024) {
        unsigned u = g_su[n][i];
        if (u) atomicAdd(&hist[u >> 20], 1u);
    }
    __syncthreads();
    if (t < 256) {
        unsigned s = 0;
#pragma unroll
        for (int j = 0; j < 16; j++) s += hist[t * 16 + j];
        psum[t] = s;
    }
    __syncthreads();
    if (t == 0) {
        unsigned total = 0;
        for (int c = 0; c < 256; c++) total += psum[c];
        if (total <= N_PRE) {
            sThr = 1;
            sB1  = -1;
            g_vcnt[n] = (int)total;
        } else {
            g_vcnt[n] = N_PRE;
            unsigned acc = 0; int c = 255;
            while (acc + psum[c] < N_PRE) { acc += psum[c]; c--; }
            int bkt = c * 16 + 15;
            while (acc + hist[bkt] < N_PRE) { acc += hist[bkt]; bkt--; }
            sB1 = bkt; sAbove = (int)acc; sThr = 0;
        }
    }
    __syncthreads();
    const int B1 = sB1;
    if (sThr == 0) {
        for (int v = t; v < 4096; v += 1024) hist[v] = 0;
        __syncthreads();
        for (int i = t; i < NA; i += 1024) {
            unsigned u = g_su[n][i];
            if (u && (int)(u >> 20) == B1) atomicAdd(&hist[(u >> 8) & 0xFFFu], 1u);
        }
        __syncthreads();
        if (t < 256) {
            unsigned s = 0;
#pragma unroll
            for (int j = 0; j < 16; j++) s += hist[t * 16 + j];
            psum[t] = s;
        }
        __syncthreads();
        if (t == 0) {
            unsigned K2 = (unsigned)(N_PRE - sAbove);
            unsigned acc = 0; int c = 255;
            while (acc + psum[c] < K2) { acc += psum[c]; c--; }
            int bkt = c * 16 + 15;
            while (acc + hist[bkt] < K2) { acc += hist[bkt]; bkt--; }
            sThr = (B1 << 12) | bkt;
        }
    }
    __syncthreads();
    const unsigned thr = (unsigned)sThr;
    if (t == 0) sCnt = 0;
    __syncthreads();
    for (int i = t; i < NA; i += 1024) {
        unsigned u = g_su[n][i];
        if (u && (u >> 8) >= thr) {
            int p = atomicAdd(&sCnt, 1);
            if (p < SORT_N)
                g_cand[n][p] = (((unsigned long long)u) << 32) | (unsigned)(~i);
        }
    }
    __syncthreads();
    if (t == 0) g_C[n] = min(sCnt, SORT_N);
}

// ---------------------------------------------------------------------------
// K4: cluster-parallel bitonic sort (unchanged)
// ---------------------------------------------------------------------------
#define SRT_T 128
#define PH(i) ((i) + ((i) >> 4))

__device__ __forceinline__ void cswap_desc(unsigned long long& a, unsigned long long& b, bool desc)
{
    bool sw = desc ? (a < b) : (a > b);
    if (sw) { unsigned long long tmp = a; a = b; b = tmp; }
}

__device__ __forceinline__ void merge16(unsigned long long v[16], bool desc)
{
#pragma unroll
    for (int jj = 8; jj >= 1; jj >>= 1)
#pragma unroll
        for (int idx = 0; idx < 16; idx++)
            if ((idx & jj) == 0) cswap_desc(v[idx], v[idx | jj], desc);
}

__device__ __forceinline__ void shfl_merge_to16(unsigned long long v[16], int t,
                                                int dmax, bool desc)
{
    for (int d = dmax; d >= 1; d >>= 1) {
        bool up = ((t & d) == 0);
        bool keepmax = (desc == up);
#pragma unroll
        for (int s = 0; s < 16; s++) {
            unsigned long long o = __shfl_xor_sync(0xFFFFFFFFu, v[s], d);
            bool agtb = v[s] > o;
            v[s] = (agtb == keepmax) ? v[s] : o;
        }
    }
    merge16(v, desc);
}

__device__ __forceinline__ void smem_phase_elem(unsigned long long* skey, int t, int j, int k)
{
#pragma unroll
    for (int p = 0; p < 16; p++) {
        int i = t + p * SRT_T;
        int l = i ^ j;
        if (l > i) {
            unsigned long long a = skey[PH(i)], b = skey[PH(l)];
            bool desc = ((i & k) == 0);
            if (desc ? (a < b) : (a > b)) { skey[PH(i)] = b; skey[PH(l)] = a; }
        }
    }
}

__device__ __forceinline__ void smem_phase_const(unsigned long long* skey, int t, int j, bool desc)
{
#pragma unroll
    for (int p = 0; p < 16; p++) {
        int i = t + p * SRT_T;
        int l = i ^ j;
        if (l > i) {
            unsigned long long a = skey[PH(i)], b = skey[PH(l)];
            if (desc ? (a < b) : (a > b)) { skey[PH(i)] = b; skey[PH(l)] = a; }
        }
    }
}

__global__ __launch_bounds__(SRT_T) __cluster_dims__(8, 1, 1)
void sort_kernel()
{
    __shared__ unsigned long long skey[2048 + 128];
    const int blk   = blockIdx.x;
    const int n     = blk >> 3;
    const int rank  = blk & 7;
    const int t     = threadIdx.x;
    const int C     = g_C[n];
    const int gb    = rank << 11;
    const int lbase = t << 4;

    unsigned long long v[16];
#pragma unroll
    for (int s = 0; s < 16; s++) {
        int gi = gb + lbase + s;
        v[s] = (gi < C) ? g_cand[n][gi] : 0ull;
    }

#pragma unroll
    for (int kk = 2; kk <= 8; kk <<= 1)
#pragma unroll
        for (int jj = kk >> 1; jj >= 1; jj >>= 1)
#pragma unroll
            for (int idx = 0; idx < 16; idx++)
                if ((idx & jj) == 0) cswap_desc(v[idx], v[idx | jj], (idx & kk) == 0);
    merge16(v, (t & 1) == 0);

    for (int k = 32; k <= 512; k <<= 1)
        shfl_merge_to16(v, t, k >> 5, ((t & (k >> 4)) == 0));

#pragma unroll
    for (int s = 0; s < 16; s++) skey[PH(lbase + s)] = v[s];
    __syncthreads();
    smem_phase_elem(skey, t, 512, 1024);
    __syncthreads();
#pragma unroll
    for (int s = 0; s < 16; s++) v[s] = skey[PH(lbase + s)];
    shfl_merge_to16(v, t, 16, ((t & 64) == 0));

    {
        bool d2 = ((rank & 1) == 0);
#pragma unroll
        for (int s = 0; s < 16; s++) skey[PH(lbase + s)] = v[s];
        __syncthreads();
        smem_phase_const(skey, t, 1024, d2);
        __syncthreads();
        smem_phase_const(skey, t, 512, d2);
        __syncthreads();
#pragma unroll
        for (int s = 0; s < 16; s++) v[s] = skey[PH(lbase + s)];
        shfl_merge_to16(v, t, 16, d2);
    }

    int pp = 0;
    for (int k = 4096; k <= SORT_N; k <<= 1) {
        bool dk = ((gb & k) == 0);
        for (int j = k >> 1; j >= 2048; j >>= 1) {
            bool lower = ((gb & j) == 0);
            bool keepmax = (dk == lower);
#pragma unroll
            for (int s = 0; s < 16; s++) skey[PH(lbase + s)] = v[s];
            __syncthreads();
            for (int i = t; i < 2048; i += SRT_T)
                g_sbuf[pp][n][gb + i] = skey[PH(i)];
            __threadfence();
            asm volatile("barrier.cluster.arrive.aligned;" ::: "memory");
            asm volatile("barrier.cluster.wait.aligned;"   ::: "memory");
            for (int i = t; i < 2048; i += SRT_T)
                skey[PH(i)] = g_sbuf[pp][n][(gb ^ j) + i];
            __syncthreads();
#pragma unroll
            for (int s = 0; s < 16; s++) {
                unsigned long long w = skey[PH(lbase + s)];
                bool agtb = v[s] > w;
                v[s] = (agtb == keepmax) ? v[s] : w;
            }
            pp ^= 1;
        }
#pragma unroll
        for (int s = 0; s < 16; s++) skey[PH(lbase + s)] = v[s];
        __syncthreads();
        smem_phase_const(skey, t, 1024, dk);
        __syncthreads();
        smem_phase_const(skey, t, 512, dk);
        __syncthreads();
#pragma unroll
        for (int s = 0; s < 16; s++) v[s] = skey[PH(lbase + s)];
        shfl_merge_to16(v, t, 16, dk);
    }

#pragma unroll
    for (int s = 0; s < 16; s++) {
        int pos = gb + lbase + s;
        if (pos < N_PRE) {
            unsigned long long kk = v[s];
            unsigned idx = ~(unsigned)(kk & 0xFFFFFFFFull);
            float4 b = (kk != 0ull) ? g_boxes[n][idx] : make_float4(0.f, 0.f, 0.f, 0.f);
            g_sboxes[n][pos] = b;
        }
    }
}

// ---------------------------------------------------------------------------
// K5: cluster-parallel chunked NMS with warp-specialized overlap.
// Per chunk: delta-vet vs new accepts -> pack/exchange dead bits -> compact ->
// phase 2 (adaptive) -> [warp0: phase-3 sweep || warps1-31: load+prevet next
// chunk vs stable accepts]. Bit-identical accept set.
// ---------------------------------------------------------------------------
#define NMS_T    1024
#define CHUNK    1024
#define SPLIT_TH 320

__device__ __forceinline__ bool iou_gt7(float2 xx, float2 yy, float a0,
                                        float2 bx, float2 by, float a1)
{
    float iw = fminf(bx.y, xx.y) - fmaxf(bx.x, xx.x);
    if (iw <= 0.f) return false;
    float ih = fminf(by.y, yy.y) - fmaxf(by.x, yy.x);
    if (ih <= 0.f) return false;
    float inter = iw * ih;
    return inter / (a0 + a1 - inter + 1e-9f) > 0.7f;   // exact reference form
}

// vet one candidate slice vs abox[j0..j1) with stride st; returns dead
__device__ __forceinline__ bool vet_range(float2 xx, float2 yy, float a0,
                                          const float4* abox, int j0, int j1, int st)
{
    float lo = 0.69f * a0;
    bool dead = false;
#pragma unroll 4
    for (int j = j0; j < j1; j += st) {
        float4 ab = abox[j];
        float a1 = (ab.z - ab.x) * (ab.w - ab.y);
        bool ok = !(a1 < lo || a0 < 0.69f * a1);
        float iw = fminf(ab.z, xx.y) - fmaxf(ab.x, xx.x);
        float ih = fminf(ab.w, yy.y) - fmaxf(ab.y, yy.x);
        if (ok && iw > 0.f && ih > 0.f) {
            float inter = iw * ih;
            if (inter / (a0 + a1 - inter + 1e-9f) > 0.7f) dead = true;
        }
    }
    return dead;
}

__global__ __launch_bounds__(NMS_T) __cluster_dims__(8, 1, 1)
void nms_kernel(float* __restrict__ out)
{
    extern __shared__ char nsm[];
    float2*        cxx    = (float2*)(nsm);                  // [2][1024]
    float2*        cyy    = (float2*)(nsm + 16384);          // [2][1024]
    float*         car    = (float*) (nsm + 32768);          // [2][1024]
    float4*        abox   = (float4*)(nsm + 40960);          // [600]
    unsigned*      sup    = (unsigned*)(nsm + 50560);        // [1024*32]
    int*           s_keep = (int*)   (nsm + 181632);         // [600]
    int*           list   = (int*)   (nsm + 184032);         // [1024]
    int*           s_wcnt = (int*)   (nsm + 188128);         // [32]
    int*           s_woff = (int*)   (nsm + 188256);         // [32]
    int*           s_kept = (int*)   (nsm + 188384);         // [1]
    int*           s_nal  = (int*)   (nsm + 188388);         // [1]
    unsigned char* s_dead = (unsigned char*)(nsm + 188392);  // [128] (rank-local)

    const int blk  = blockIdx.x;
    const int n    = blk >> 3;
    const int rank = blk & 7;
    const int t    = threadIdx.x;
    const int vcnt = g_vcnt[n];

    if (t == 0) *s_kept = 0;
    if (t < 128) s_dead[t] = 0;
    {   // preload chunk 0 into buffer 0
        int C0 = min(CHUNK, vcnt);
        if (t < C0) {
            float4 b = g_sboxes[n][t];
            cxx[t] = make_float2(b.x, b.z);
            cyy[t] = make_float2(b.y, b.w);
            car[t] = fmaxf(b.z - b.x, 0.f) * fmaxf(b.w - b.y, 0.f);
        }
    }
    __syncthreads();

    int preK = 0;
    int cc = 0;
    for (int base = 0; base < vcnt; base += CHUNK, cc++) {
        const int kept0 = *s_kept;               // identical on all ranks
        if (kept0 >= N_POST) break;              // uniform across cluster
        const int C = min(CHUNK, vcnt - base);
        const int par = cc & 1;
        const int bo = par << 10;                // buffer offset

        // delta-vet rank's 128 candidates vs the NEW accepts [preK, kept0)
        if (kept0 > preK) {
            const int ci = t >> 3;               // 0..127
            const int cand = (rank << 7) + ci;
            const int sub = t & 7;
            if (cand < C) {
                bool dead = vet_range(cxx[bo + cand], cyy[bo + cand], car[bo + cand],
                                      abox, preK + sub, kept0, 8);
                if (dead) s_dead[ci] = 1;        // benign same-value race
            }
        }
        __syncthreads();

        // pack 128 dead bits -> global; clear s_dead for the coming prevet
        if (t < 128) {
            bool d = s_dead[t] != 0;
            unsigned bal = __ballot_sync(0xFFFFFFFFu, d);
            if ((t & 31) == 0) g_deadw[n][par][rank][t >> 5] = bal;
            s_dead[t] = 0;
        }
        __threadfence();
        asm volatile("barrier.cluster.arrive.aligned;" ::: "memory");
        asm volatile("barrier.cluster.wait.aligned;"   ::: "memory");

        // stable compaction of survivors (dead bits from all ranks)
        bool alive;
        int  pfx;
        {
            unsigned w = g_deadw[n][par][t >> 7][(t >> 5) & 3];
            bool isdead = (w >> (t & 31)) & 1u;
            alive = (t < C) && !isdead;
            unsigned bal = __ballot_sync(0xFFFFFFFFu, alive);
            pfx = __popc(bal & ((1u << (t & 31)) - 1u));
            if ((t & 31) == 0) s_wcnt[t >> 5] = __popc(bal);
        }
        __syncthreads();
        if (t == 0) {
            int acc = 0;
#pragma unroll
            for (int w = 0; w < 32; w++) { s_woff[w] = acc; acc += s_wcnt[w]; }
            *s_nal = acc;
        }
        __syncthreads();
        if (alive) list[s_woff[t >> 5] + pfx] = t;
        __syncthreads();

        const int nAlive = *s_nal;
        const int W = (nAlive + 31) >> 5;

        if (nAlive > SPLIT_TH) {
            // phase 2 SPLIT: rank computes its row slice, exchange via global
            int rowsPer = (nAlive + 7) >> 3;
            int r0 = rank * rowsPer;
            int r1 = min(r0 + rowsPer, nAlive);
            int nTasks = (r1 - r0) * W;
            for (int u = t; u < nTasks; u += NMS_T) {
                int row = r0 + u / W;
                int cw  = u - (row - r0) * W;
                int i   = list[row];
                float2 xx = cxx[bo + i];
                float2 yy = cyy[bo + i];
                float a0 = car[bo + i];
                unsigned bits = 0;
                int cbase = cw << 5;
                int jmax = min(32, nAlive - cbase);
                for (int j = 0; j < jmax; j++) {
                    int cidx = cbase + j;
                    if (cidx <= row) continue;
                    int col = list[cidx];
                    float a1 = car[bo + col];
                    if (a1 < 0.69f * a0 || a0 < 0.69f * a1) continue;
                    if (iou_gt7(xx, yy, a0, cxx[bo + col], cyy[bo + col], a1)) bits |= 1u << j;
                }
                g_supg[par][n][(row << 5) + cw] = bits;
            }
            __threadfence();
            asm volatile("barrier.cluster.arrive.aligned;" ::: "memory");
            asm volatile("barrier.cluster.wait.aligned;"   ::: "memory");
            for (int idx = t; idx < (nAlive << 5); idx += NMS_T) {
                if ((idx & 31) < W) sup[idx] = g_supg[par][n][idx];
            }
            __syncthreads();
        } else {
            // phase 2 LOCAL: full upper triangle redundantly in smem
            for (int u = t; u < nAlive * W; u += NMS_T) {
                int row = u / W;
                int cw  = u - row * W;
                int i   = list[row];
                float2 xx = cxx[bo + i];
                float2 yy = cyy[bo + i];
                float a0 = car[bo + i];
                unsigned bits = 0;
                int cbase = cw << 5;
                int jmax = min(32, nAlive - cbase);
                for (int j = 0; j < jmax; j++) {
                    int cidx = cbase + j;
                    if (cidx <= row) continue;
                    int col = list[cidx];
                    float a1 = car[bo + col];
                    if (a1 < 0.69f * a0 || a0 < 0.69f * a1) continue;
                    if (iou_gt7(xx, yy, a0, cxx[bo + col], cyy[bo + col], a1)) bits |= 1u << j;
                }
                sup[(row << 5) + cw] = bits;
            }
            __syncthreads();
        }

        // ---- OVERLAP: warp 0 = phase-3 sweep; warps 1-31 = load+prevet next chunk
        const int nb = base + CHUNK;
        const bool haveNext = (nb < vcnt);       // uniform
        if (t < 32) {
            // phase 3 (redundant, deterministic): bitmap sweep
            int kept = kept0;
            unsigned w16 = 0;
            if (t < W) {
                int rem = nAlive - (t << 5);
                w16 = (rem >= 32) ? 0xFFFFFFFFu : ((1u << rem) - 1u);
            }
            while (kept < N_POST) {
                unsigned nz = __ballot_sync(0xFFFFFFFFu, w16 != 0);
                if (!nz) break;
                int wi = __ffs(nz) - 1;
                unsigned wv = __shfl_sync(0xFFFFFFFFu, w16, wi);
                int bit = __ffs(wv) - 1;
                int r = (wi << 5) + bit;
                int i = list[r];
                if (t == 0) {
                    float2 xx = cxx[bo + i];
                    float2 yy = cyy[bo + i];
                    abox[kept] = make_float4(xx.x, yy.x, xx.y, yy.y);
                    s_keep[kept] = base + i;
                }
                kept++;
                unsigned su_ = (t < W) ? sup[(r << 5) + t] : 0u;
                w16 &= ~su_;
                if (t == wi) w16 &= ~(1u << bit);
            }
            if (t == 0) *s_kept = kept;
        } else if (haveNext) {
            const int Cn = min(CHUNK, vcnt - nb);
            const int bn = (par ^ 1) << 10;
            for (int i = t - 32; i < CHUNK; i += 992) {
                if (i < Cn) {
                    float4 b = g_sboxes[n][nb + i];
                    cxx[bn + i] = make_float2(b.x, b.z);
                    cyy[bn + i] = make_float2(b.y, b.w);
                    car[bn + i] = fmaxf(b.z - b.x, 0.f) * fmaxf(b.w - b.y, 0.f);
                }
            }
            asm volatile("bar.sync 1, 992;" ::: "memory");
            if (t >= 256 && kept0 > 0) {
                int u = t - 256;                 // 0..767
                int ci = u / 6;                  // 0..127 (6 threads/cand)
                int sub = u - ci * 6;
                int cand = (rank << 7) + ci;
                if (cand < Cn) {
                    bool dead = vet_range(cxx[bn + cand], cyy[bn + cand], car[bn + cand],
                                          abox, sub, kept0, 6);   // stable prefix only
                    if (dead) s_dead[ci] = 1;
                }
            }
        }
        __syncthreads();
        preK = kept0;    // next chunk's delta-vet starts where this prevet stopped
    }

    if (rank == 0) {
        const int kept = *s_kept;
        for (int e = t; e < N_POST; e += NMS_T) {
            int ki = (e < kept) ? s_keep[e] : (e - kept);   // pad like the reference
            float4 b = g_sboxes[n][ki];
            *(float4*)(out + OFF_ROIS + n * (N_POST * 4) + e * 4) = b;
        }
    }
}

#define NMS_SMEM 188544

// ---------------------------------------------------------------------------
extern "C" void kernel_launch(void* const* d_in, const int* in_sizes, int n_in,
                              void* d_out, int out_size)
{
    const float* x   = (const float*)d_in[0];
    const float* wsc = (const float*)d_in[1];
    const float* bsc = (const float*)d_in[2];
    const float* wlc = (const float*)d_in[3];
    const float* blc = (const float*)d_in[4];
    float* out = (float*)d_out;

    cudaFuncSetAttribute(nms_kernel, cudaFuncAttributeMaxDynamicSharedMemorySize, NMS_SMEM);

    gemm_kernel<<<256, 128>>>(x, wsc, bsc, wlc, blc, out);
    select_kernel<<<NB, 1024>>>();
    sort_kernel<<<NB * 8, SRT_T>>>();
    nms_kernel<<<NB * 8, NMS_T, NMS_SMEM>>>(out);
}

// round 16
// speedup vs baseline: 1.1689x; 1.1689x over previous
#include <cuda_runtime.h>
#include <cuda_bf16.h>
#include <cstdint>

// ---------------------------------------------------------------------------
// RPN: fused GEMM+decode -> top-12000 radix select -> cluster-parallel bitonic
// sort (8 CTAs/batch) -> cluster-parallel chunked NMS (8 CTAs/batch,
// CHUNK=1024, ballot dead-mask, compacted-SoA phase 2 with diagonal skip).
// Outputs: rpn_locs[8,36864,4] | rpn_scores[8,36864,2] | rois[8,600,4] | anchor[1,36864,4]
// Score GEMM accumulation = splitK2 (bit-matches reference); loc GEMM = plain chain.
// ---------------------------------------------------------------------------

#define NB        8
#define NA        36864
#define HW        4096
#define K_DIM     512
#define N_PRE     12000
#define N_POST    600
#define SORT_N    16384

#define OFF_SCORES 1179648
#define OFF_ROIS   1769472
#define OFF_ANCH   1788672

__device__ float4             g_boxes[NB][NA];
__device__ unsigned           g_su[NB][NA];
__device__ unsigned long long g_cand[NB][SORT_N];
__device__ int                g_C[NB];
__device__ int                g_vcnt[NB];
__device__ float4             g_sboxes[NB][N_PRE];
__device__ unsigned           g_deadw[NB][2][8][4];      // 128 dead bits per rank
__device__ unsigned           g_supg[2][NB][1024 * 32];  // phase-2 sup exchange (split path)
__device__ unsigned long long g_sbuf[2][NB][SORT_N];     // sort cross-CTA ping-pong

__constant__ float c_aw[9] = {181.01933598375618f, 362.03867196751236f, 724.0773439350247f,
                              128.0f, 256.0f, 512.0f,
                              90.50966799187809f, 181.01933598375618f, 362.03867196751236f};
__constant__ float c_ah[9] = {90.50966799187809f, 181.01933598375618f, 362.03867196751236f,
                              128.0f, 256.0f, 512.0f,
                              181.01933598375618f, 362.03867196751236f, 724.0773439350247f};

// ---------------------------------------------------------------------------
// packed f32x2 helpers
// ---------------------------------------------------------------------------
__device__ __forceinline__ unsigned long long fma2(unsigned long long a,
                                                   unsigned long long b,
                                                   unsigned long long c)
{
    unsigned long long d;
    asm("fma.rn.f32x2 %0, %1, %2, %3;" : "=l"(d) : "l"(a), "l"(b), "l"(c));
    return d;
}
__device__ __forceinline__ unsigned long long packxx(float x)
{
    unsigned long long r;
    unsigned xi = __float_as_uint(x);
    asm("mov.b64 %0, {%1, %2};" : "=l"(r) : "r"(xi), "r"(xi));
    return r;
}
__device__ __forceinline__ float f2lo(unsigned long long u) { return __uint_as_float((unsigned)u); }
__device__ __forceinline__ float f2hi(unsigned long long u) { return __uint_as_float((unsigned)(u >> 32)); }

__device__ __forceinline__ void gemm_inner(const float* xs,
                                           const unsigned long long* ws2, int t,
                                           unsigned long long (&accp)[18],
                                           unsigned long long (&scp)[9])
{
#pragma unroll 4
    for (int kk = 0; kk < 64; kk++) {
        unsigned long long xp = packxx(xs[kk * 128 + t]);
#pragma unroll
        for (int o2 = 0; o2 < 18; o2++)
            accp[o2] = fma2(ws2[o2 * 64 + kk], xp, accp[o2]);
#pragma unroll
        for (int o2 = 0; o2 < 9; o2++)
            scp[o2] = fma2(ws2[(18 + o2) * 64 + kk], xp, scp[o2]);
    }
}

// ---------------------------------------------------------------------------
// K1: fused GEMM + decode epilogue (unchanged)
// ---------------------------------------------------------------------------
__global__ __launch_bounds__(128) void gemm_kernel(
    const float* __restrict__ x,
    const float* __restrict__ wsc, const float* __restrict__ bsc,
    const float* __restrict__ wlc, const float* __restrict__ blc,
    float* __restrict__ out)
{
    __shared__ float xs[64 * 128];
    __shared__ unsigned long long ws2[27 * 64];
    const int t   = threadIdx.x;
    const int b   = blockIdx.x;
    const int n   = b >> 5;
    const int hw0 = (b & 31) * 128;
    const float* xb = x + n * (K_DIM * HW) + hw0;

    unsigned long long accp[18], sp0[9], sp1[9];
#pragma unroll
    for (int o = 0; o < 18; o++) accp[o] = 0ull;
#pragma unroll
    for (int o = 0; o < 9; o++) { sp0[o] = 0ull; sp1[o] = 0ull; }

    for (int k0 = 0; k0 < K_DIM; k0 += 64) {
#pragma unroll
        for (int it = 0; it < 16; it++) {
            int v = t + it * 128;
            int r = v >> 5;
            int c = v & 31;
            float4 val = *(const float4*)(xb + (k0 + r) * HW + c * 4);
            *(float4*)&xs[r * 128 + c * 4] = val;
        }
        for (int v = t; v < 864; v += 128) {
            int o = v >> 4;
            int c = v & 15;
            const float* row = (o < 36) ? (wlc + o * K_DIM) : (wsc + (o - 36) * K_DIM);
            float4 w = *(const float4*)(row + k0 + c * 4);
            float* dst = (float*)&ws2[(o >> 1) * 64 + c * 4];
            int half = o & 1;
            dst[0 + half] = w.x;
            dst[2 + half] = w.y;
            dst[4 + half] = w.z;
            dst[6 + half] = w.w;
        }
        __syncthreads();

        if (k0 < 256) gemm_inner(xs, ws2, t, accp, sp0);
        else          gemm_inner(xs, ws2, t, accp, sp1);
        __syncthreads();
    }

    const int hw = hw0 + t;
    float lv[36], sv[18];
#pragma unroll
    for (int o2 = 0; o2 < 18; o2++) {
        lv[2 * o2]     = f2lo(accp[o2]) + blc[2 * o2];
        lv[2 * o2 + 1] = f2hi(accp[o2]) + blc[2 * o2 + 1];
    }
#pragma unroll
    for (int o2 = 0; o2 < 9; o2++) {
        sv[2 * o2]     = (f2lo(sp0[o2]) + f2lo(sp1[o2])) + bsc[2 * o2];
        sv[2 * o2 + 1] = (f2hi(sp0[o2]) + f2hi(sp1[o2])) + bsc[2 * o2 + 1];
    }

    float* lout = out + n * (NA * 4) + hw * 36;
#pragma unroll
    for (int o = 0; o < 36; o++) lout[o] = lv[o];
    float* sout = out + OFF_SCORES + n * (NA * 2) + hw * 18;
#pragma unroll
    for (int o = 0; o < 18; o++) sout[o] = sv[o];

    float sx = (float)((hw & 63) * 16);
    float sy = (float)((hw >> 6) * 16);
#pragma unroll
    for (int a = 0; a < 9; a++) {
        int i = hw * 9 + a;
        float aw = c_aw[a], ah = c_ah[a];
        float ax1 = sx - 0.5f * aw, ay1 = sy - 0.5f * ah;
        float ax2 = sx + 0.5f * aw, ay2 = sy + 0.5f * ah;
        if (n == 0)
            *(float4*)(out + OFF_ANCH + i * 4) = make_float4(ax1, ay1, ax2, ay2);

        float aww = ax2 - ax1, ahh = ay2 - ay1;
        float acx = ax1 + 0.5f * aww, acy = ay1 + 0.5f * ahh;

        float cx = lv[a * 4 + 0] * aww + acx;
        float cy = lv[a * 4 + 1] * ahh + acy;
        float w  = expf(lv[a * 4 + 2]) * aww;
        float h  = expf(lv[a * 4 + 3]) * ahh;

        float x1 = fminf(fmaxf(cx - 0.5f * w, 0.0f), 1024.0f);
        float y1 = fminf(fmaxf(cy - 0.5f * h, 0.0f), 1024.0f);
        float x2 = fminf(fmaxf(cx + 0.5f * w, 0.0f), 1024.0f);
        float y2 = fminf(fmaxf(cy + 0.5f * h, 0.0f), 1024.0f);

        bool valid = ((x2 - x1) >= 16.0f) && ((y2 - y1) >= 16.0f);

        float s0 = sv[a * 2], s1 = sv[a * 2 + 1];
        float m  = fmaxf(s0, s1);
        float e0 = expf(s0 - m), e1 = expf(s1 - m);
        float fg = e1 / (e0 + e1);

        g_su[n][i]    = valid ? (__float_as_uint(fg) | 0x80000000u) : 0u;
        g_boxes[n][i] = make_float4(x1, y1, x2, y2);
    }
}

// ---------------------------------------------------------------------------
// K3: radix select (unchanged)
// ---------------------------------------------------------------------------
__global__ __launch_bounds__(1024) void select_kernel()
{
    __shared__ unsigned hist[4096];
    __shared__ unsigned psum[256];
    __shared__ int sB1, sAbove, sThr, sCnt;

    const int n = blockIdx.x;
    const int t = threadIdx.x;

    for (int v = t; v < 4096; v += 1024) hist[v] = 0;
    __syncthreads();
    for (int i = t; i < NA; i += 1024) {
        unsigned u = g_su[n][i];
        if (u) atomicAdd(&hist[u >> 20], 1u);
    }
    __syncthreads();
    if (t < 256) {
        unsigned s = 0;
#pragma unroll
        for (int j = 0; j < 16; j++) s += hist[t * 16 + j];
        psum[t] = s;
    }
    __syncthreads();
    if (t == 0) {
        unsigned total = 0;
        for (int c = 0; c < 256; c++) total += psum[c];
        if (total <= N_PRE) {
            sThr = 1;
            sB1  = -1;
            g_vcnt[n] = (int)total;
        } else {
            g_vcnt[n] = N_PRE;
            unsigned acc = 0; int c = 255;
            while (acc + psum[c] < N_PRE) { acc += psum[c]; c--; }
            int bkt = c * 16 + 15;
            while (acc + hist[bkt] < N_PRE) { acc += hist[bkt]; bkt--; }
            sB1 = bkt; sAbove = (int)acc; sThr = 0;
        }
    }
    __syncthreads();
    const int B1 = sB1;
    if (sThr == 0) {
        for (int v = t; v < 4096; v += 1024) hist[v] = 0;
        __syncthreads();
        for (int i = t; i < NA; i += 1024) {
            unsigned u = g_su[n][i];
            if (u && (int)(u >> 20) == B1) atomicAdd(&hist[(u >> 8) & 0xFFFu], 1u);
        }
        __syncthreads();
        if (t < 256) {
            unsigned s = 0;
#pragma unroll
            for (int j = 0; j < 16; j++) s += hist[t * 16 + j];
            psum[t] = s;
        }
        __syncthreads();
        if (t == 0) {
            unsigned K2 = (unsigned)(N_PRE - sAbove);
            unsigned acc = 0; int c = 255;
            while (acc + psum[c] < K2) { acc += psum[c]; c--; }
            int bkt = c * 16 + 15;
            while (acc + hist[bkt] < K2) { acc += hist[bkt]; bkt--; }
            sThr = (B1 << 12) | bkt;
        }
    }
    __syncthreads();
    const unsigned thr = (unsigned)sThr;
    if (t == 0) sCnt = 0;
    __syncthreads();
    for (int i = t; i < NA; i += 1024) {
        unsigned u = g_su[n][i];
        if (u && (u >> 8) >= thr) {
            int p = atomicAdd(&sCnt, 1);
            if (p < SORT_N)
                g_cand[n][p] = (((unsigned long long)u) << 32) | (unsigned)(~i);
        }
    }
    __syncthreads();
    if (t == 0) g_C[n] = min(sCnt, SORT_N);
}

// ---------------------------------------------------------------------------
// K4: cluster-parallel bitonic sort (unchanged)
// ---------------------------------------------------------------------------
#define SRT_T 128
#define PH(i) ((i) + ((i) >> 4))

__device__ __forceinline__ void cswap_desc(unsigned long long& a, unsigned long long& b, bool desc)
{
    bool sw = desc ? (a < b) : (a > b);
    if (sw) { unsigned long long tmp = a; a = b; b = tmp; }
}

__device__ __forceinline__ void merge16(unsigned long long v[16], bool desc)
{
#pragma unroll
    for (int jj = 8; jj >= 1; jj >>= 1)
#pragma unroll
        for (int idx = 0; idx < 16; idx++)
            if ((idx & jj) == 0) cswap_desc(v[idx], v[idx | jj], desc);
}

__device__ __forceinline__ void shfl_merge_to16(unsigned long long v[16], int t,
                                                int dmax, bool desc)
{
    for (int d = dmax; d >= 1; d >>= 1) {
        bool up = ((t & d) == 0);
        bool keepmax = (desc == up);
#pragma unroll
        for (int s = 0; s < 16; s++) {
            unsigned long long o = __shfl_xor_sync(0xFFFFFFFFu, v[s], d);
            bool agtb = v[s] > o;
            v[s] = (agtb == keepmax) ? v[s] : o;
        }
    }
    merge16(v, desc);
}

__device__ __forceinline__ void smem_phase_elem(unsigned long long* skey, int t, int j, int k)
{
#pragma unroll
    for (int p = 0; p < 16; p++) {
        int i = t + p * SRT_T;
        int l = i ^ j;
        if (l > i) {
            unsigned long long a = skey[PH(i)], b = skey[PH(l)];
            bool desc = ((i & k) == 0);
            if (desc ? (a < b) : (a > b)) { skey[PH(i)] = b; skey[PH(l)] = a; }
        }
    }
}

__device__ __forceinline__ void smem_phase_const(unsigned long long* skey, int t, int j, bool desc)
{
#pragma unroll
    for (int p = 0; p < 16; p++) {
        int i = t + p * SRT_T;
        int l = i ^ j;
        if (l > i) {
            unsigned long long a = skey[PH(i)], b = skey[PH(l)];
            if (desc ? (a < b) : (a > b)) { skey[PH(i)] = b; skey[PH(l)] = a; }
        }
    }
}

__global__ __launch_bounds__(SRT_T) __cluster_dims__(8, 1, 1)
void sort_kernel()
{
    __shared__ unsigned long long skey[2048 + 128];
    const int blk   = blockIdx.x;
    const int n     = blk >> 3;
    const int rank  = blk & 7;
    const int t     = threadIdx.x;
    const int C     = g_C[n];
    const int gb    = rank << 11;
    const int lbase = t << 4;

    unsigned long long v[16];
#pragma unroll
    for (int s = 0; s < 16; s++) {
        int gi = gb + lbase + s;
        v[s] = (gi < C) ? g_cand[n][gi] : 0ull;
    }

#pragma unroll
    for (int kk = 2; kk <= 8; kk <<= 1)
#pragma unroll
        for (int jj = kk >> 1; jj >= 1; jj >>= 1)
#pragma unroll
            for (int idx = 0; idx < 16; idx++)
                if ((idx & jj) == 0) cswap_desc(v[idx], v[idx | jj], (idx & kk) == 0);
    merge16(v, (t & 1) == 0);

    for (int k = 32; k <= 512; k <<= 1)
        shfl_merge_to16(v, t, k >> 5, ((t & (k >> 4)) == 0));

#pragma unroll
    for (int s = 0; s < 16; s++) skey[PH(lbase + s)] = v[s];
    __syncthreads();
    smem_phase_elem(skey, t, 512, 1024);
    __syncthreads();
#pragma unroll
    for (int s = 0; s < 16; s++) v[s] = skey[PH(lbase + s)];
    shfl_merge_to16(v, t, 16, ((t & 64) == 0));

    {
        bool d2 = ((rank & 1) == 0);
#pragma unroll
        for (int s = 0; s < 16; s++) skey[PH(lbase + s)] = v[s];
        __syncthreads();
        smem_phase_const(skey, t, 1024, d2);
        __syncthreads();
        smem_phase_const(skey, t, 512, d2);
        __syncthreads();
#pragma unroll
        for (int s = 0; s < 16; s++) v[s] = skey[PH(lbase + s)];
        shfl_merge_to16(v, t, 16, d2);
    }

    int pp = 0;
    for (int k = 4096; k <= SORT_N; k <<= 1) {
        bool dk = ((gb & k) == 0);
        for (int j = k >> 1; j >= 2048; j >>= 1) {
            bool lower = ((gb & j) == 0);
            bool keepmax = (dk == lower);
#pragma unroll
            for (int s = 0; s < 16; s++) skey[PH(lbase + s)] = v[s];
            __syncthreads();
            for (int i = t; i < 2048; i += SRT_T)
                g_sbuf[pp][n][gb + i] = skey[PH(i)];
            __threadfence();
            asm volatile("barrier.cluster.arrive.aligned;" ::: "memory");
            asm volatile("barrier.cluster.wait.aligned;"   ::: "memory");
            for (int i = t; i < 2048; i += SRT_T)
                skey[PH(i)] = g_sbuf[pp][n][(gb ^ j) + i];
            __syncthreads();
#pragma unroll
            for (int s = 0; s < 16; s++) {
                unsigned long long w = skey[PH(lbase + s)];
                bool agtb = v[s] > w;
                v[s] = (agtb == keepmax) ? v[s] : w;
            }
            pp ^= 1;
        }
#pragma unroll
        for (int s = 0; s < 16; s++) skey[PH(lbase + s)] = v[s];
        __syncthreads();
        smem_phase_const(skey, t, 1024, dk);
        __syncthreads();
        smem_phase_const(skey, t, 512, dk);
        __syncthreads();
#pragma unroll
        for (int s = 0; s < 16; s++) v[s] = skey[PH(lbase + s)];
        shfl_merge_to16(v, t, 16, dk);
    }

#pragma unroll
    for (int s = 0; s < 16; s++) {
        int pos = gb + lbase + s;
        if (pos < N_PRE) {
            unsigned long long kk = v[s];
            unsigned idx = ~(unsigned)(kk & 0xFFFFFFFFull);
            float4 b = (kk != 0ull) ? g_boxes[n][idx] : make_float4(0.f, 0.f, 0.f, 0.f);
            g_sboxes[n][pos] = b;
        }
    }
}

// ---------------------------------------------------------------------------
// K5: cluster-parallel chunked NMS. CHUNK=1024. Ballot dead-mask.
// Phase 1: early exit at 4-group granularity.
// Phase 2: compacted SoA (dxx/dyy/dar) + diagonal skip; adaptive split.
// Phase 3: warp-0 bitmap sweep (redundant, deterministic).
// ---------------------------------------------------------------------------
#define NMS_T    1024
#define CHUNK    1024
#define SPLIT_TH 320

__global__ __launch_bounds__(NMS_T) __cluster_dims__(8, 1, 1)
void nms_kernel(float* __restrict__ out)
{
    extern __shared__ char nsm[];
    float2*        cxx    = (float2*)(nsm);                  // [1024]
    float2*        cyy    = (float2*)(nsm + 8192);           // [1024]
    float*         car    = (float*) (nsm + 16384);          // [1024]
    float4*        abox   = (float4*)(nsm + 20480);          // [600]
    unsigned*      sup    = (unsigned*)(nsm + 30080);        // [1024*32]
    int*           s_keep = (int*)   (nsm + 161152);         // [600]
    int*           list   = (int*)   (nsm + 163552);         // [1024]
    float2*        dxx    = (float2*)(nsm + 167648);         // [1024] compacted
    float2*        dyy    = (float2*)(nsm + 175840);         // [1024]
    float*         dar    = (float*) (nsm + 184032);         // [1024]
    int*           s_wcnt = (int*)   (nsm + 188128);         // [32]
    int*           s_woff = (int*)   (nsm + 188256);         // [32]
    int*           s_kept = (int*)   (nsm + 188384);         // [1]
    int*           s_nal  = (int*)   (nsm + 188388);         // [1]
    unsigned char* s_dead = (unsigned char*)(nsm + 188392);  // [1024]

    const int blk  = blockIdx.x;
    const int n    = blk >> 3;
    const int rank = blk & 7;
    const int t    = threadIdx.x;
    const int vcnt = g_vcnt[n];

    if (t == 0) *s_kept = 0;
    __syncthreads();

    int cc = 0;
    for (int base = 0; base < vcnt; base += CHUNK, cc++) {
        const int kept0 = *s_kept;               // identical on all ranks
        if (kept0 >= N_POST) break;              // uniform across cluster
        const int C = min(CHUNK, vcnt - base);
        const int par = cc & 1;

        // load chunk candidates
        if (t < C) {
            float4 b = g_sboxes[n][base + t];
            cxx[t] = make_float2(b.x, b.z);
            cyy[t] = make_float2(b.y, b.w);
            car[t] = fmaxf(b.z - b.x, 0.f) * fmaxf(b.w - b.y, 0.f);
        }
        __syncthreads();

        // phase 1: rank vets its 128 candidates (8 threads/cand), ballot reduce;
        // early exit at 4-group granularity (deterministic).
        {
            const int cand = (rank << 7) + (t >> 3);
            const int sub  = t & 3;              // note: 8 threads/cand, 2 lanes share sub pattern
            bool dead = false;
            if (cand < C && kept0 > 0) {
                float2 xx = cxx[cand];
                float2 yy = cyy[cand];
                float a0 = car[cand];
                float lo = 0.69f * a0;
                int jj = (t & 7);
                while (jj < kept0 && !dead) {
#pragma unroll
                    for (int u = 0; u < 4; u++) {
                        if (jj < kept0) {
                            float4 ab = abox[jj];
                            float a1 = (ab.z - ab.x) * (ab.w - ab.y);
                            bool ok = !(a1 < lo || a0 < 0.69f * a1);
                            float iw = fminf(ab.z, xx.y) - fmaxf(ab.x, xx.x);
                            float ih = fminf(ab.w, yy.y) - fmaxf(ab.y, yy.x);
                            if (ok && iw > 0.f && ih > 0.f) {
                                float inter = iw * ih;
                                if (inter / (a0 + a1 - inter + 1e-9f) > 0.7f) dead = true;
                            }
                        }
                        jj += 8;
                    }
                }
            }
            (void)sub;
            unsigned gmask = 0xFFu << (t & 24);
            bool any = __any_sync(gmask, dead);
            if ((t & 7) == 0) s_dead[(rank << 7) + (t >> 3)] = any ? 1 : 0;
        }
        __syncthreads();

        // pack our 128 dead bits -> global (4 warps, ballot each)
        if (t < 128) {
            bool d = s_dead[(rank << 7) + t] != 0;
            unsigned bal = __ballot_sync(0xFFFFFFFFu, d);
            if ((t & 31) == 0) g_deadw[n][par][rank][t >> 5] = bal;
        }
        __threadfence();
        asm volatile("barrier.cluster.arrive.aligned;" ::: "memory");
        asm volatile("barrier.cluster.wait.aligned;"   ::: "memory");

        // stable compaction of survivors (dead bits from all ranks)
        bool alive;
        int  pfx;
        {
            unsigned w = g_deadw[n][par][t >> 7][(t >> 5) & 3];
            bool isdead = (w >> (t & 31)) & 1u;
            alive = (t < C) && !isdead;
            unsigned bal = __ballot_sync(0xFFFFFFFFu, alive);
            pfx = __popc(bal & ((1u << (t & 31)) - 1u));
            if ((t & 31) == 0) s_wcnt[t >> 5] = __popc(bal);
        }
        __syncthreads();
        if (t == 0) {
            int acc = 0;
#pragma unroll
            for (int w = 0; w < 32; w++) { s_woff[w] = acc; acc += s_wcnt[w]; }
            *s_nal = acc;
        }
        __syncthreads();
        if (alive) {
            int r = s_woff[t >> 5] + pfx;
            list[r] = t;
            dxx[r] = cxx[t];
            dyy[r] = cyy[t];
            dar[r] = car[t];
        }
        __syncthreads();

        const int nAlive = *s_nal;
        const int W = (nAlive + 31) >> 5;

        if (nAlive > SPLIT_TH) {
            // phase 2 SPLIT: rank computes its row slice, exchange via global
            int rowsPer = (nAlive + 7) >> 3;
            int r0 = rank * rowsPer;
            int r1 = min(r0 + rowsPer, nAlive);
            int nTasks = (r1 - r0) * W;
            for (int u = t; u < nTasks; u += NMS_T) {
                int row = r0 + u / W;
                int cw  = u - (row - r0) * W;
                int cbase = cw << 5;
                int jmax = min(32, nAlive - cbase);
                unsigned bits = 0;
                if (cbase + jmax - 1 > row) {       // word has entries above diagonal
                    float2 xx = dxx[row];
                    float2 yy = dyy[row];
                    float a0 = dar[row];
                    int j0 = max(0, row + 1 - cbase);
                    for (int j = j0; j < jmax; j++) {
                        int cidx = cbase + j;
                        float a1 = dar[cidx];
                        if (a1 < 0.69f * a0 || a0 < 0.69f * a1) continue;
                        float2 bx = dxx[cidx];
                        float iw = fminf(bx.y, xx.y) - fmaxf(bx.x, xx.x);
                        if (iw <= 0.f) continue;
                        float2 by = dyy[cidx];
                        float ih = fminf(by.y, yy.y) - fmaxf(by.x, yy.x);
                        if (ih <= 0.f) continue;
                        float inter = iw * ih;
                        if (inter / (a0 + a1 - inter + 1e-9f) > 0.7f) bits |= 1u << j;
                    }
                }
                g_supg[par][n][(row << 5) + cw] = bits;
            }
            __threadfence();
            asm volatile("barrier.cluster.arrive.aligned;" ::: "memory");
            asm volatile("barrier.cluster.wait.aligned;"   ::: "memory");
            for (int idx = t; idx < (nAlive << 5); idx += NMS_T) {
                if ((idx & 31) < W) sup[idx] = g_supg[par][n][idx];
            }
            __syncthreads();
        } else {
            // phase 2 LOCAL: full upper triangle redundantly in smem
            for (int u = t; u < nAlive * W; u += NMS_T) {
                int row = u / W;
                int cw  = u - row * W;
                int cbase = cw << 5;
                int jmax = min(32, nAlive - cbase);
                unsigned bits = 0;
                if (cbase + jmax - 1 > row) {
                    float2 xx = dxx[row];
                    float2 yy = dyy[row];
                    float a0 = dar[row];
                    int j0 = max(0, row + 1 - cbase);
                    for (int j = j0; j < jmax; j++) {
                        int cidx = cbase + j;
                        float a1 = dar[cidx];
                        if (a1 < 0.69f * a0 || a0 < 0.69f * a1) continue;
                        float2 bx = dxx[cidx];
                        float iw = fminf(bx.y, xx.y) - fmaxf(bx.x, xx.x);
                        if (iw <= 0.f) continue;
                        float2 by = dyy[cidx];
                        float ih = fminf(by.y, yy.y) - fmaxf(by.x, yy.x);
                        if (ih <= 0.f) continue;
                        float inter = iw * ih;
                        if (inter / (a0 + a1 - inter + 1e-9f) > 0.7f) bits |= 1u << j;
                    }
                }
                sup[(row << 5) + cw] = bits;
            }
            __syncthreads();
        }

        // phase 3 (redundant, deterministic): warp-0 bitmap sweep
        if (t < 32) {
            int kept = kept0;
            unsigned w16 = 0;
            if (t < W) {
                int rem = nAlive - (t << 5);
                w16 = (rem >= 32) ? 0xFFFFFFFFu : ((1u << rem) - 1u);
            }
            while (kept < N_POST) {
                unsigned nz = __ballot_sync(0xFFFFFFFFu, w16 != 0);
                if (!nz) break;
                int wi = __ffs(nz) - 1;
                unsigned wv = __shfl_sync(0xFFFFFFFFu, w16, wi);
                int bit = __ffs(wv) - 1;
                int r = (wi << 5) + bit;
                if (t == 0) {
                    float2 xx = dxx[r];
                    float2 yy = dyy[r];
                    abox[kept] = make_float4(xx.x, yy.x, xx.y, yy.y);
                    s_keep[kept] = base + list[r];
                }
                kept++;
                unsigned su_ = (t < W) ? sup[(r << 5) + t] : 0u;
                w16 &= ~su_;
                if (t == wi) w16 &= ~(1u << bit);
            }
            if (t == 0) *s_kept = kept;
        }
        __syncthreads();
    }

    if (rank == 0) {
        const int kept = *s_kept;
        for (int e = t; e < N_POST; e += NMS_T) {
            int ki = (e < kept) ? s_keep[e] : (e - kept);   // pad like the reference
            float4 b = g_sboxes[n][ki];
            *(float4*)(out + OFF_ROIS + n * (N_POST * 4) + e * 4) = b;
        }
    }
}

#define NMS_SMEM 189440

// ---------------------------------------------------------------------------
extern "C" void kernel_launch(void* const* d_in, const int* in_sizes, int n_in,
                              void* d_out, int out_size)
{
    const float* x   = (const float*)d_in[0];
    const float* wsc = (const float*)d_in[1];
    const float* bsc = (const float*)d_in[2];
    const float* wlc = (const float*)d_in[3];
    const float* blc = (const float*)d_in[4];
    float* out = (float*)d_out;

    cudaFuncSetAttribute(nms_kernel, cudaFuncAttributeMaxDynamicSharedMemorySize, NMS_SMEM);

    gemm_kernel<<<256, 128>>>(x, wsc, bsc, wlc, blc, out);
    select_kernel<<<NB, 1024>>>();
    sort_kernel<<<NB * 8, SRT_T>>>();
    nms_kernel<<<NB * 8, NMS_T, NMS_SMEM>>>(out);
}